// round 2
// baseline (speedup 1.0000x reference)
#include <cuda_runtime.h>
#include <cuda_bf16.h>
#include <math.h>

#define NTOK 2048
#define DMODEL 512
#define NHEADS 8
#define DHEAD 64
#define ITERS 5

// ---------------- scratch (device globals; no allocations allowed) ----------------
__device__ float g_Q[NTOK * DMODEL];
__device__ float g_K[NTOK * DMODEL];
__device__ float g_V[NTOK * DMODEL];
__device__ float g_S[(size_t)NHEADS * NTOK * NTOK];   // scores, later overwritten with attn
__device__ float g_X[NTOK * DMODEL];                  // attn @ V (pre out-projection)
__device__ float g_xyz[2 * NTOK * 3];                 // ping-pong xyz
__device__ float g_M[NHEADS * NTOK];                  // per-(head,row) running max (final iter)
__device__ float g_Lsum[NHEADS * NTOK];               // per-(head,row) softmax denom (final iter)

// ---------------- generic tiled SGEMM, NT form: C = alpha * A(MxK) * B(NxK)^T + bias ----------------
template<int BM, int BN, int BK, int TM, int TN>
__global__ void sgemm_nt(int K,
                         const float* __restrict__ A, int lda, long sA,
                         const float* __restrict__ B, int ldb, long sB,
                         float* __restrict__ C, int ldc, long sC,
                         const float* __restrict__ bias, float alpha)
{
    constexpr int THREADS = (BM / TM) * (BN / TN);
    A += (long)blockIdx.z * sA;
    B += (long)blockIdx.z * sB;
    C += (long)blockIdx.z * sC;

    __shared__ float As[BK][BM];
    __shared__ float Bs[BK][BN];

    const int tid = threadIdx.x;
    const int tcol = tid % (BN / TN);
    const int trow = tid / (BN / TN);
    const int row0 = blockIdx.y * BM;
    const int col0 = blockIdx.x * BN;

    float acc[TM][TN];
#pragma unroll
    for (int i = 0; i < TM; i++)
#pragma unroll
        for (int j = 0; j < TN; j++) acc[i][j] = 0.f;

    for (int k0 = 0; k0 < K; k0 += BK) {
#pragma unroll
        for (int i = tid; i < BM * BK; i += THREADS) {
            int m = i / BK, kk = i % BK;
            As[kk][m] = A[(long)(row0 + m) * lda + k0 + kk];
        }
#pragma unroll
        for (int i = tid; i < BN * BK; i += THREADS) {
            int n = i / BK, kk = i % BK;
            Bs[kk][n] = B[(long)(col0 + n) * ldb + k0 + kk];
        }
        __syncthreads();
#pragma unroll
        for (int kk = 0; kk < BK; kk++) {
            float a[TM], b[TN];
#pragma unroll
            for (int i = 0; i < TM; i++) a[i] = As[kk][trow * TM + i];
#pragma unroll
            for (int j = 0; j < TN; j++) b[j] = Bs[kk][tcol * TN + j];
#pragma unroll
            for (int i = 0; i < TM; i++)
#pragma unroll
                for (int j = 0; j < TN; j++) acc[i][j] = fmaf(a[i], b[j], acc[i][j]);
        }
        __syncthreads();
    }

#pragma unroll
    for (int i = 0; i < TM; i++) {
#pragma unroll
        for (int j = 0; j < TN; j++) {
            int cc = col0 + tcol * TN + j;
            float v = alpha * acc[i][j];
            if (bias) v += bias[cc];
            C[(long)(row0 + trow * TM + i) * ldc + cc] = v;
        }
    }
}

// ---------------- generic tiled SGEMM, NN form: C = A(MxK) * B(KxN) ----------------
template<int BM, int BN, int BK, int TM, int TN>
__global__ void sgemm_nn(int K,
                         const float* __restrict__ A, int lda, long sA,
                         const float* __restrict__ B, int ldb, long sB,
                         float* __restrict__ C, int ldc, long sC)
{
    constexpr int THREADS = (BM / TM) * (BN / TN);
    A += (long)blockIdx.z * sA;
    B += (long)blockIdx.z * sB;
    C += (long)blockIdx.z * sC;

    __shared__ float As[BK][BM];
    __shared__ float Bs[BK][BN];

    const int tid = threadIdx.x;
    const int tcol = tid % (BN / TN);
    const int trow = tid / (BN / TN);
    const int row0 = blockIdx.y * BM;
    const int col0 = blockIdx.x * BN;

    float acc[TM][TN];
#pragma unroll
    for (int i = 0; i < TM; i++)
#pragma unroll
        for (int j = 0; j < TN; j++) acc[i][j] = 0.f;

    for (int k0 = 0; k0 < K; k0 += BK) {
#pragma unroll
        for (int i = tid; i < BM * BK; i += THREADS) {
            int m = i / BK, kk = i % BK;
            As[kk][m] = A[(long)(row0 + m) * lda + k0 + kk];
        }
#pragma unroll
        for (int i = tid; i < BK * BN; i += THREADS) {
            int kk = i / BN, n = i % BN;
            Bs[kk][n] = B[(long)(k0 + kk) * ldb + col0 + n];
        }
        __syncthreads();
#pragma unroll
        for (int kk = 0; kk < BK; kk++) {
            float a[TM], b[TN];
#pragma unroll
            for (int i = 0; i < TM; i++) a[i] = As[kk][trow * TM + i];
#pragma unroll
            for (int j = 0; j < TN; j++) b[j] = Bs[kk][tcol * TN + j];
#pragma unroll
            for (int i = 0; i < TM; i++)
#pragma unroll
                for (int j = 0; j < TN; j++) acc[i][j] = fmaf(a[i], b[j], acc[i][j]);
        }
        __syncthreads();
    }

#pragma unroll
    for (int i = 0; i < TM; i++)
#pragma unroll
        for (int j = 0; j < TN; j++)
            C[(long)(row0 + trow * TM + i) * ldc + col0 + tcol * TN + j] = acc[i][j];
}

// ---------------- mean-shift step: online softmax per (head,row), xyz update ----------------
// grid = NTOK blocks (one row n), 256 threads = 8 warps (one per head).
__global__ void step_kernel(const float* __restrict__ S,
                            const float* __restrict__ xyz_in,
                            float* __restrict__ xyz_out,
                            const float* __restrict__ yhat,
                            const int* __restrict__ mask,
                            const float* __restrict__ tptr,
                            const float* __restrict__ bwptr,
                            float* __restrict__ Mbuf,
                            float* __restrict__ Lbuf)
{
    const int n = blockIdx.x;
    const int tid = threadIdx.x;
    const int warp = tid >> 5;
    const int lane = tid & 31;

    __shared__ float Lsh[256], xs[256], ys[256], zs[256];
    __shared__ float red[NHEADS][3];

    const float invTemp = 1.0f / tptr[0];
    const float bw = bwptr[0];
    const float cbw = 1.0f / (2.0f * bw * bw);
    const float xn = xyz_in[n * 3 + 0];
    const float yn = xyz_in[n * 3 + 1];
    const float zn = xyz_in[n * 3 + 2];
    const float sqn = xn * xn + yn * yn + zn * zn;

    float run_max = -1e30f, sum = 0.f, ax = 0.f, ay = 0.f, az = 0.f;
    const float* Srow = S + ((long)warp * NTOK + n) * NTOK;

    for (int t0 = 0; t0 < NTOK; t0 += 256) {
        __syncthreads();
        {
            int m = t0 + tid;
            float x = xyz_in[m * 3 + 0];
            float y = xyz_in[m * 3 + 1];
            float z = xyz_in[m * 3 + 2];
            float d2 = sqn + (x * x + y * y + z * z) - 2.f * (xn * x + yn * y + zn * z);
            float kern = __expf(-d2 * cbw);
            float lw = __logf(kern * yhat[m] + 1e-9f);
            if (mask[(long)n * NTOK + m] <= 0) lw = -3e9f;
            Lsh[tid] = lw; xs[tid] = x; ys[tid] = y; zs[tid] = z;
        }
        __syncthreads();
#pragma unroll
        for (int c = 0; c < 8; c++) {
            int j = c * 32 + lane;
            float lw = Lsh[j];
            float logit = (lw < -1e9f) ? -1e9f : fmaf(Srow[t0 + j], invTemp, lw);
            float cm = logit;
#pragma unroll
            for (int o = 16; o; o >>= 1) cm = fmaxf(cm, __shfl_xor_sync(0xffffffffu, cm, o));
            float nm = fmaxf(run_max, cm);
            float scale = __expf(run_max - nm);
            float p = __expf(logit - nm);
            sum = sum * scale + p;
            ax = ax * scale + p * xs[j];
            ay = ay * scale + p * ys[j];
            az = az * scale + p * zs[j];
            run_max = nm;
        }
    }

#pragma unroll
    for (int o = 16; o; o >>= 1) {
        sum += __shfl_xor_sync(0xffffffffu, sum, o);
        ax  += __shfl_xor_sync(0xffffffffu, ax, o);
        ay  += __shfl_xor_sync(0xffffffffu, ay, o);
        az  += __shfl_xor_sync(0xffffffffu, az, o);
    }
    if (lane == 0) {
        Mbuf[warp * NTOK + n] = run_max;
        Lbuf[warp * NTOK + n] = sum;
        float inv = 1.0f / sum;
        red[warp][0] = ax * inv;
        red[warp][1] = ay * inv;
        red[warp][2] = az * inv;
    }
    __syncthreads();
    if (tid == 0) {
        float X = 0.f, Y = 0.f, Z = 0.f;
#pragma unroll
        for (int h = 0; h < NHEADS; h++) { X += red[h][0]; Y += red[h][1]; Z += red[h][2]; }
        xyz_out[n * 3 + 0] = X * 0.125f;
        xyz_out[n * 3 + 1] = Y * 0.125f;
        xyz_out[n * 3 + 2] = Z * 0.125f;
    }
}

// ---------------- final-iteration pass 2: overwrite S with normalized attn ----------------
__global__ void write_attn(float* __restrict__ S,
                           const float* __restrict__ xyz_in,
                           const float* __restrict__ yhat,
                           const int* __restrict__ mask,
                           const float* __restrict__ tptr,
                           const float* __restrict__ bwptr,
                           const float* __restrict__ Mbuf,
                           const float* __restrict__ Lbuf)
{
    const int n = blockIdx.x;
    const int tid = threadIdx.x;
    const int warp = tid >> 5;
    const int lane = tid & 31;

    __shared__ float Lsh[256];

    const float invTemp = 1.0f / tptr[0];
    const float bw = bwptr[0];
    const float cbw = 1.0f / (2.0f * bw * bw);
    const float xn = xyz_in[n * 3 + 0];
    const float yn = xyz_in[n * 3 + 1];
    const float zn = xyz_in[n * 3 + 2];
    const float sqn = xn * xn + yn * yn + zn * zn;

    const float Mh = Mbuf[warp * NTOK + n];
    const float invL = 1.0f / Lbuf[warp * NTOK + n];
    float* Srow = S + ((long)warp * NTOK + n) * NTOK;

    for (int t0 = 0; t0 < NTOK; t0 += 256) {
        __syncthreads();
        {
            int m = t0 + tid;
            float x = xyz_in[m * 3 + 0];
            float y = xyz_in[m * 3 + 1];
            float z = xyz_in[m * 3 + 2];
            float d2 = sqn + (x * x + y * y + z * z) - 2.f * (xn * x + yn * y + zn * z);
            float kern = __expf(-d2 * cbw);
            float lw = __logf(kern * yhat[m] + 1e-9f);
            if (mask[(long)n * NTOK + m] <= 0) lw = -3e9f;
            Lsh[tid] = lw;
        }
        __syncthreads();
#pragma unroll
        for (int c = 0; c < 8; c++) {
            int j = c * 32 + lane;
            float lw = Lsh[j];
            float p;
            if (lw < -1e9f) {
                p = 0.0f;
            } else {
                float logit = fmaf(Srow[t0 + j], invTemp, lw);
                p = __expf(logit - Mh) * invL;
            }
            Srow[t0 + j] = p;
        }
    }
}

// ---------------- host orchestration ----------------
extern "C" void kernel_launch(void* const* d_in, const int* in_sizes, int n_in,
                              void* d_out, int out_size)
{
    const float* xyz  = (const float*)d_in[0];
    const float* strf = (const float*)d_in[1];
    // d_in[2] esm_feat: dead code in reference, skipped
    const float* yhat = (const float*)d_in[3];
    const int*   mask = (const int*)d_in[4];
    const float* t    = (const float*)d_in[5];
    const float* bw   = (const float*)d_in[6];
    // d_in[7] max_iter == 5 (graph must be static; hardcoded)
    const float* Wq = (const float*)d_in[8];
    const float* bq = (const float*)d_in[9];
    const float* Wk = (const float*)d_in[10];
    const float* bk = (const float*)d_in[11];
    const float* Wv = (const float*)d_in[12];
    const float* bv = (const float*)d_in[13];
    const float* Wo = (const float*)d_in[14];
    const float* bo = (const float*)d_in[15];

    float *Q, *K, *V, *S, *X, *xyzb, *Mb, *Lb;
    cudaGetSymbolAddress((void**)&Q, g_Q);
    cudaGetSymbolAddress((void**)&K, g_K);
    cudaGetSymbolAddress((void**)&V, g_V);
    cudaGetSymbolAddress((void**)&S, g_S);
    cudaGetSymbolAddress((void**)&X, g_X);
    cudaGetSymbolAddress((void**)&xyzb, g_xyz);
    cudaGetSymbolAddress((void**)&Mb, g_M);
    cudaGetSymbolAddress((void**)&Lb, g_Lsum);

    float* xyz0 = xyzb;
    float* xyz1 = xyzb + NTOK * 3;
    float* outp = (float*)d_out;

    cudaMemcpyAsync(xyz0, xyz, NTOK * 3 * sizeof(float), cudaMemcpyDeviceToDevice);

    dim3 blk(256);

    // Q, K, V projections: C = X @ W^T + b   (2048 x 512 x 512, NT)
    sgemm_nt<128,128,16,8,8><<<dim3(DMODEL/128, NTOK/128, 1), blk>>>(
        DMODEL, strf, DMODEL, 0L, Wq, DMODEL, 0L, Q, DMODEL, 0L, bq, 1.0f);
    sgemm_nt<128,128,16,8,8><<<dim3(DMODEL/128, NTOK/128, 1), blk>>>(
        DMODEL, strf, DMODEL, 0L, Wk, DMODEL, 0L, K, DMODEL, 0L, bk, 1.0f);
    sgemm_nt<128,128,16,8,8><<<dim3(DMODEL/128, NTOK/128, 1), blk>>>(
        DMODEL, strf, DMODEL, 0L, Wv, DMODEL, 0L, V, DMODEL, 0L, bv, 1.0f);

    // scores: S[h] = Qh @ Kh^T * (1/sqrt(64))  (batched NT, K=64)
    sgemm_nt<128,128,16,8,8><<<dim3(NTOK/128, NTOK/128, NHEADS), blk>>>(
        DHEAD, Q, DMODEL, (long)DHEAD, K, DMODEL, (long)DHEAD,
        S, NTOK, (long)NTOK * NTOK, nullptr, 0.125f);

    // 5 mean-shift iterations (ping-pong xyz)
    for (int it = 0; it < ITERS; it++) {
        const float* xin = (it & 1) ? xyz1 : xyz0;
        float*       xo  = (it & 1) ? xyz0 : xyz1;
        step_kernel<<<NTOK, blk>>>(S, xin, xo, yhat, mask, t, bw, Mb, Lb);
    }
    // Final attn computed from xyz state BEFORE the last step (xyz0 after 4 flips)
    write_attn<<<NTOK, blk>>>(S, xyz0, yhat, mask, t, bw, Mb, Lb);

    // X[h] = P[h] @ V[h]  (batched NN: 2048 x 64 x 2048)
    sgemm_nn<128,64,16,8,4><<<dim3(1, NTOK/128, NHEADS), blk>>>(
        NTOK, S, NTOK, (long)NTOK * NTOK, V, DMODEL, (long)DHEAD,
        X, DMODEL, (long)DHEAD);

    // out = X @ Wo^T + bo -> second part of d_out
    sgemm_nt<128,128,16,8,8><<<dim3(DMODEL/128, NTOK/128, 1), blk>>>(
        DMODEL, X, DMODEL, 0L, Wo, DMODEL, 0L, outp + NTOK * 3, DMODEL, 0L, bo, 1.0f);

    // xyz after 5 iterations is in xyz1 -> first part of d_out
    cudaMemcpyAsync(outp, xyz1, NTOK * 3 * sizeof(float), cudaMemcpyDeviceToDevice);
}

// round 4
// speedup vs baseline: 2.1725x; 2.1725x over previous
#include <cuda_runtime.h>
#include <cuda_bf16.h>
#include <math.h>

#define NTOK 2048
#define DMODEL 512
#define NQKV 1536
#define NHEADS 8
#define DHEAD 64
#define ITERS 5

// ---------------- scratch (device globals) ----------------
__device__ float g_QKV[NTOK * NQKV];                   // packed Q|K|V
__device__ float g_W[NQKV * DMODEL];                   // packed Wq|Wk|Wv
__device__ float g_b[NQKV];
__device__ float g_E[(size_t)NHEADS * NTOK * NTOK];    // exp(S/temp); later overwritten with attn P
__device__ float g_X[NTOK * DMODEL];                   // P @ V
__device__ float g_xyz[2 * NTOK * 3];

// ================= NT GEMM: C = alpha*A(MxK)*B(NxK)^T [+bias | exp epilogue] =================
template<int BM, int BN, int BK, int TM, int TN, bool EXPE>
__global__ void __launch_bounds__((BM/TM)*(BN/TN), 2)
gemm_nt(int K,
        const float* __restrict__ A, int lda, long sA,
        const float* __restrict__ B, int ldb, long sB,
        float* __restrict__ C, int ldc, long sC,
        const float* __restrict__ bias, float alpha,
        const float* __restrict__ tptr)
{
    constexpr int THREADS = (BM/TM)*(BN/TN);
    constexpr int KV = BK/4;
    __shared__ float As[BK][BM];
    __shared__ float Bs[BK][BN];

    A += (long)blockIdx.z * sA;
    B += (long)blockIdx.z * sB;
    C += (long)blockIdx.z * sC;

    const int tid  = threadIdx.x;
    const int tcol = tid % (BN/TN);
    const int trow = tid / (BN/TN);
    const int row0 = blockIdx.y * BM;
    const int col0 = blockIdx.x * BN;

    float acc[TM][TN];
#pragma unroll
    for (int i = 0; i < TM; i++)
#pragma unroll
        for (int j = 0; j < TN; j++) acc[i][j] = 0.f;

    for (int k0 = 0; k0 < K; k0 += BK) {
#pragma unroll
        for (int i = tid; i < BM*KV; i += THREADS) {
            int m = i / KV, kv = i % KV;
            float4 v = *(const float4*)(A + (long)(row0+m)*lda + k0 + kv*4);
            As[kv*4+0][m] = v.x; As[kv*4+1][m] = v.y;
            As[kv*4+2][m] = v.z; As[kv*4+3][m] = v.w;
        }
#pragma unroll
        for (int i = tid; i < BN*KV; i += THREADS) {
            int nn = i / KV, kv = i % KV;
            float4 v = *(const float4*)(B + (long)(col0+nn)*ldb + k0 + kv*4);
            Bs[kv*4+0][nn] = v.x; Bs[kv*4+1][nn] = v.y;
            Bs[kv*4+2][nn] = v.z; Bs[kv*4+3][nn] = v.w;
        }
        __syncthreads();
#pragma unroll
        for (int kk = 0; kk < BK; kk++) {
            float a[TM], b[TN];
#pragma unroll
            for (int i = 0; i < TM; i += 4)
                *(float4*)&a[i] = *(const float4*)&As[kk][trow*TM + i];
#pragma unroll
            for (int j = 0; j < TN; j += 4)
                *(float4*)&b[j] = *(const float4*)&Bs[kk][tcol*TN + j];
#pragma unroll
            for (int i = 0; i < TM; i++)
#pragma unroll
                for (int j = 0; j < TN; j++)
                    acc[i][j] = fmaf(a[i], b[j], acc[i][j]);
        }
        __syncthreads();
    }

    float scale = alpha;
    if (EXPE) scale *= 1.0f / tptr[0];

#pragma unroll
    for (int i = 0; i < TM; i++) {
        long r = row0 + trow*TM + i;
#pragma unroll
        for (int j = 0; j < TN; j += 4) {
            int c = col0 + tcol*TN + j;
            float4 v;
            v.x = acc[i][j+0]*scale; v.y = acc[i][j+1]*scale;
            v.z = acc[i][j+2]*scale; v.w = acc[i][j+3]*scale;
            if (EXPE) {
                v.x = __expf(v.x); v.y = __expf(v.y);
                v.z = __expf(v.z); v.w = __expf(v.w);
            } else if (bias) {
                float4 bb = *(const float4*)&bias[c];
                v.x += bb.x; v.y += bb.y; v.z += bb.z; v.w += bb.w;
            }
            *(float4*)&C[r*ldc + c] = v;
        }
    }
}

// ================= NN GEMM: C = A(MxK)*B(KxN) =================
template<int BM, int BN, int BK, int TM, int TN>
__global__ void __launch_bounds__((BM/TM)*(BN/TN), 2)
gemm_nn(int K,
        const float* __restrict__ A, int lda, long sA,
        const float* __restrict__ B, int ldb, long sB,
        float* __restrict__ C, int ldc, long sC)
{
    constexpr int THREADS = (BM/TM)*(BN/TN);
    constexpr int KV = BK/4;
    constexpr int NV = BN/4;
    __shared__ float As[BK][BM];
    __shared__ float Bs[BK][BN];

    A += (long)blockIdx.z * sA;
    B += (long)blockIdx.z * sB;
    C += (long)blockIdx.z * sC;

    const int tid  = threadIdx.x;
    const int tcol = tid % (BN/TN);
    const int trow = tid / (BN/TN);
    const int row0 = blockIdx.y * BM;
    const int col0 = blockIdx.x * BN;

    float acc[TM][TN];
#pragma unroll
    for (int i = 0; i < TM; i++)
#pragma unroll
        for (int j = 0; j < TN; j++) acc[i][j] = 0.f;

    for (int k0 = 0; k0 < K; k0 += BK) {
#pragma unroll
        for (int i = tid; i < BM*KV; i += THREADS) {
            int m = i / KV, kv = i % KV;
            float4 v = *(const float4*)(A + (long)(row0+m)*lda + k0 + kv*4);
            As[kv*4+0][m] = v.x; As[kv*4+1][m] = v.y;
            As[kv*4+2][m] = v.z; As[kv*4+3][m] = v.w;
        }
#pragma unroll
        for (int i = tid; i < BK*NV; i += THREADS) {
            int kk = i / NV, nv = i % NV;
            float4 v = *(const float4*)(B + (long)(k0+kk)*ldb + col0 + nv*4);
            *(float4*)&Bs[kk][nv*4] = v;
        }
        __syncthreads();
#pragma unroll
        for (int kk = 0; kk < BK; kk++) {
            float a[TM], b[TN];
#pragma unroll
            for (int i = 0; i < TM; i += 4)
                *(float4*)&a[i] = *(const float4*)&As[kk][trow*TM + i];
#pragma unroll
            for (int j = 0; j < TN; j += 4)
                *(float4*)&b[j] = *(const float4*)&Bs[kk][tcol*TN + j];
#pragma unroll
            for (int i = 0; i < TM; i++)
#pragma unroll
                for (int j = 0; j < TN; j++)
                    acc[i][j] = fmaf(a[i], b[j], acc[i][j]);
        }
        __syncthreads();
    }

#pragma unroll
    for (int i = 0; i < TM; i++) {
        long r = row0 + trow*TM + i;
#pragma unroll
        for (int j = 0; j < TN; j += 4)
            *(float4*)&C[r*ldc + col0 + tcol*TN + j] = *(float4*)&acc[i][j];
    }
}

// ================= mean-shift step =================
// E holds exp(S/temp) (iteration-invariant). attn = E*w / Z with
// w(n,m) = mask ? kern*yhat+eps : 0 (head-independent, shared by all 8 warps).
// grid = NTOK blocks, 256 threads = 8 head-warps. FINAL: also overwrite E with attn.
template<bool FINAL>
__global__ void __launch_bounds__(256)
step_kernel(float* __restrict__ E,
            const float* __restrict__ xyz_in,
            float* __restrict__ xyz_out,
            const float* __restrict__ yhat,
            const int* __restrict__ mask,
            const float* __restrict__ bwptr)
{
    __shared__ float xs[NTOK], ys[NTOK], zs[NTOK], ws[NTOK];
    __shared__ float red[NHEADS][3];

    const int n    = blockIdx.x;
    const int tid  = threadIdx.x;
    const int warp = tid >> 5;
    const int lane = tid & 31;

    const float bw  = bwptr[0];
    const float cbw = 1.0f / (2.0f * bw * bw);
    const float xn = xyz_in[n*3+0];
    const float yn = xyz_in[n*3+1];
    const float zn = xyz_in[n*3+2];
    const float sqn = xn*xn + yn*yn + zn*zn;
    const int* mrow = mask + (long)n * NTOK;

    for (int m = tid; m < NTOK; m += 256) {
        float x = xyz_in[m*3+0];
        float y = xyz_in[m*3+1];
        float z = xyz_in[m*3+2];
        xs[m] = x; ys[m] = y; zs[m] = z;
        float d2 = sqn + (x*x + y*y + z*z) - 2.f*(xn*x + yn*y + zn*z);
        float w = __expf(-d2 * cbw) * yhat[m] + 1e-9f;
        ws[m] = (mrow[m] > 0) ? w : 0.f;
    }
    __syncthreads();

    float4* Erow = (float4*)(E + ((long)warp * NTOK + n) * NTOK);

    float Z = 0.f, ax = 0.f, ay = 0.f, az = 0.f;
#pragma unroll 8
    for (int it = 0; it < NTOK/128; it++) {
        int j4 = it*32 + lane;
        float4 e = Erow[j4];
        int j = j4*4;
        float4 w  = *(const float4*)&ws[j];
        float4 X  = *(const float4*)&xs[j];
        float4 Y  = *(const float4*)&ys[j];
        float4 Zc = *(const float4*)&zs[j];
        float p0 = e.x*w.x, p1 = e.y*w.y, p2 = e.z*w.z, p3 = e.w*w.w;
        Z  += (p0 + p1) + (p2 + p3);
        ax = fmaf(p0, X.x, fmaf(p1, X.y, fmaf(p2, X.z, fmaf(p3, X.w, ax))));
        ay = fmaf(p0, Y.x, fmaf(p1, Y.y, fmaf(p2, Y.z, fmaf(p3, Y.w, ay))));
        az = fmaf(p0, Zc.x, fmaf(p1, Zc.y, fmaf(p2, Zc.z, fmaf(p3, Zc.w, az))));
    }

#pragma unroll
    for (int o = 16; o; o >>= 1) {
        Z  += __shfl_xor_sync(0xffffffffu, Z, o);
        ax += __shfl_xor_sync(0xffffffffu, ax, o);
        ay += __shfl_xor_sync(0xffffffffu, ay, o);
        az += __shfl_xor_sync(0xffffffffu, az, o);
    }

    if (FINAL) {
        // overwrite E with normalized attention P = E*w/Z (same xyz state & Z as this step)
        float invZ = 1.0f / Z;
#pragma unroll 8
        for (int it = 0; it < NTOK/128; it++) {
            int j4 = it*32 + lane;
            float4 e = Erow[j4];
            int j = j4*4;
            float4 w = *(const float4*)&ws[j];
            e.x = e.x * w.x * invZ;
            e.y = e.y * w.y * invZ;
            e.z = e.z * w.z * invZ;
            e.w = e.w * w.w * invZ;
            Erow[j4] = e;
        }
    }

    if (lane == 0) {
        float iZ = 1.0f / Z;
        red[warp][0] = ax * iZ;
        red[warp][1] = ay * iZ;
        red[warp][2] = az * iZ;
    }
    __syncthreads();
    if (tid == 0) {
        float X = 0.f, Y = 0.f, W = 0.f;
#pragma unroll
        for (int h = 0; h < NHEADS; h++) { X += red[h][0]; Y += red[h][1]; W += red[h][2]; }
        xyz_out[n*3+0] = X * 0.125f;
        xyz_out[n*3+1] = Y * 0.125f;
        xyz_out[n*3+2] = W * 0.125f;
    }
}

// ================= host orchestration =================
extern "C" void kernel_launch(void* const* d_in, const int* in_sizes, int n_in,
                              void* d_out, int out_size)
{
    const float* xyz  = (const float*)d_in[0];
    const float* strf = (const float*)d_in[1];
    // d_in[2] esm_feat: dead code in reference
    const float* yhat = (const float*)d_in[3];
    const int*   mask = (const int*)d_in[4];
    const float* t    = (const float*)d_in[5];
    const float* bw   = (const float*)d_in[6];
    // d_in[7] max_iter == 5 (static graph)
    const float* Wq = (const float*)d_in[8];
    const float* bq = (const float*)d_in[9];
    const float* Wk = (const float*)d_in[10];
    const float* bk = (const float*)d_in[11];
    const float* Wv = (const float*)d_in[12];
    const float* bv = (const float*)d_in[13];
    const float* Wo = (const float*)d_in[14];
    const float* bo = (const float*)d_in[15];

    float *QKV, *Wb, *bb, *E, *X, *xyzb;
    cudaGetSymbolAddress((void**)&QKV,  g_QKV);
    cudaGetSymbolAddress((void**)&Wb,   g_W);
    cudaGetSymbolAddress((void**)&bb,   g_b);
    cudaGetSymbolAddress((void**)&E,    g_E);
    cudaGetSymbolAddress((void**)&X,    g_X);
    cudaGetSymbolAddress((void**)&xyzb, g_xyz);

    float* xyz0 = xyzb;
    float* xyz1 = xyzb + NTOK*3;
    float* outp = (float*)d_out;
    const size_t WSZ = (size_t)DMODEL * DMODEL * sizeof(float);

    // pack weights/biases for fused QKV GEMM
    cudaMemcpyAsync(Wb + 0*DMODEL*DMODEL, Wq, WSZ, cudaMemcpyDeviceToDevice);
    cudaMemcpyAsync(Wb + 1*DMODEL*DMODEL, Wk, WSZ, cudaMemcpyDeviceToDevice);
    cudaMemcpyAsync(Wb + 2*DMODEL*DMODEL, Wv, WSZ, cudaMemcpyDeviceToDevice);
    cudaMemcpyAsync(bb + 0*DMODEL, bq, DMODEL*sizeof(float), cudaMemcpyDeviceToDevice);
    cudaMemcpyAsync(bb + 1*DMODEL, bk, DMODEL*sizeof(float), cudaMemcpyDeviceToDevice);
    cudaMemcpyAsync(bb + 2*DMODEL, bv, DMODEL*sizeof(float), cudaMemcpyDeviceToDevice);
    cudaMemcpyAsync(xyz0, xyz, NTOK*3*sizeof(float), cudaMemcpyDeviceToDevice);

    dim3 blk(256);

    // fused QKV projection: [2048 x 1536] = strf @ Wpacked^T + bpacked
    gemm_nt<128,128,32,8,8,false><<<dim3(NQKV/128, NTOK/128, 1), blk>>>(
        DMODEL, strf, DMODEL, 0L, Wb, DMODEL, 0L,
        QKV, NQKV, 0L, bb, 1.0f, nullptr);

    // E[h] = exp( (Qh @ Kh^T) / (8*temp) )   (batched NT, K=64, exp epilogue)
    gemm_nt<128,128,32,8,8,true><<<dim3(NTOK/128, NTOK/128, NHEADS), blk>>>(
        DHEAD, QKV, NQKV, (long)DHEAD, QKV + DMODEL, NQKV, (long)DHEAD,
        E, NTOK, (long)NTOK*NTOK, nullptr, 0.125f, t);

    // 5 mean-shift iterations; final one also writes normalized attn P over E
    step_kernel<false><<<NTOK, blk>>>(E, xyz0, xyz1, yhat, mask, bw);
    step_kernel<false><<<NTOK, blk>>>(E, xyz1, xyz0, yhat, mask, bw);
    step_kernel<false><<<NTOK, blk>>>(E, xyz0, xyz1, yhat, mask, bw);
    step_kernel<false><<<NTOK, blk>>>(E, xyz1, xyz0, yhat, mask, bw);
    step_kernel<true ><<<NTOK, blk>>>(E, xyz0, xyz1, yhat, mask, bw);

    // X[h] = P[h] @ V[h]   (batched NN: 2048 x 64 x 2048) — 256 CTAs for better SM fill
    gemm_nn<64,64,32,4,4><<<dim3(1, NTOK/64, NHEADS), blk>>>(
        NTOK, E, NTOK, (long)NTOK*NTOK, QKV + 2*DMODEL, NQKV, (long)DHEAD,
        X, DMODEL, (long)DHEAD);

    // out = X @ Wo^T + bo
    gemm_nt<64,128,32,4,8,false><<<dim3(DMODEL/128, NTOK/64, 1), blk>>>(
        DMODEL, X, DMODEL, 0L, Wo, DMODEL, 0L,
        outp + NTOK*3, DMODEL, 0L, bo, 1.0f, nullptr);

    // xyz after 5 iterations -> first part of d_out
    cudaMemcpyAsync(outp, xyz1, NTOK*3*sizeof(float), cudaMemcpyDeviceToDevice);
}

// round 9
// speedup vs baseline: 3.4023x; 1.5660x over previous
#include <cuda_runtime.h>
#include <cuda_bf16.h>
#include <cuda_fp16.h>
#include <math.h>

#define NTOK 2048
#define DMODEL 512
#define NQKV 1536
#define NHEADS 8
#define DHEAD 64

// ---------------- scratch (device globals) ----------------
__device__ float  g_QKV[NTOK * NQKV];                   // packed Q|K|V (f32)
__device__ __half g_QKVh[NTOK * NQKV];                  // packed Q|K|V (fp16)
__device__ float  g_W[NQKV * DMODEL];                   // packed Wq|Wk|Wv
__device__ float  g_b[NQKV];
__device__ __half g_E[(size_t)NHEADS * NTOK * NTOK];    // exp(S/temp) fp16; later attn P
__device__ float  g_X[NTOK * DMODEL];                   // P @ V (f32)
__device__ float  g_xyz[2 * NTOK * 3];

__device__ __forceinline__ void mma_f16(float* c, unsigned a0, unsigned a1, unsigned a2, unsigned a3,
                                        unsigned b0, unsigned b1) {
    asm volatile("mma.sync.aligned.m16n8k16.row.col.f32.f16.f16.f32 "
                 "{%0,%1,%2,%3},{%4,%5,%6,%7},{%8,%9},{%0,%1,%2,%3};"
                 : "+f"(c[0]), "+f"(c[1]), "+f"(c[2]), "+f"(c[3])
                 : "r"(a0), "r"(a1), "r"(a2), "r"(a3), "r"(b0), "r"(b1));
}

// ================= f32 NT GEMM (QKV + out projection): C = A*B^T + bias =================
template<int BM, int BN, int BK, int TM, int TN>
__global__ void __launch_bounds__((BM/TM)*(BN/TN), 2)
gemm_nt(int K,
        const float* __restrict__ A, int lda,
        const float* __restrict__ B, int ldb,
        float* __restrict__ C, int ldc,
        const float* __restrict__ bias)
{
    constexpr int THREADS = (BM/TM)*(BN/TN);
    constexpr int KV = BK/4;
    __shared__ float As[BK][BM];
    __shared__ float Bs[BK][BN];

    const int tid  = threadIdx.x;
    const int tcol = tid % (BN/TN);
    const int trow = tid / (BN/TN);
    const int row0 = blockIdx.y * BM;
    const int col0 = blockIdx.x * BN;

    float acc[TM][TN];
#pragma unroll
    for (int i = 0; i < TM; i++)
#pragma unroll
        for (int j = 0; j < TN; j++) acc[i][j] = 0.f;

    for (int k0 = 0; k0 < K; k0 += BK) {
#pragma unroll
        for (int i = tid; i < BM*KV; i += THREADS) {
            int m = i / KV, kv = i % KV;
            float4 v = *(const float4*)(A + (long)(row0+m)*lda + k0 + kv*4);
            As[kv*4+0][m] = v.x; As[kv*4+1][m] = v.y;
            As[kv*4+2][m] = v.z; As[kv*4+3][m] = v.w;
        }
#pragma unroll
        for (int i = tid; i < BN*KV; i += THREADS) {
            int nn = i / KV, kv = i % KV;
            float4 v = *(const float4*)(B + (long)(col0+nn)*ldb + k0 + kv*4);
            Bs[kv*4+0][nn] = v.x; Bs[kv*4+1][nn] = v.y;
            Bs[kv*4+2][nn] = v.z; Bs[kv*4+3][nn] = v.w;
        }
        __syncthreads();
#pragma unroll
        for (int kk = 0; kk < BK; kk++) {
            float a[TM], b[TN];
#pragma unroll
            for (int i = 0; i < TM; i += 4)
                *(float4*)&a[i] = *(const float4*)&As[kk][trow*TM + i];
#pragma unroll
            for (int j = 0; j < TN; j += 4)
                *(float4*)&b[j] = *(const float4*)&Bs[kk][tcol*TN + j];
#pragma unroll
            for (int i = 0; i < TM; i++)
#pragma unroll
                for (int j = 0; j < TN; j++)
                    acc[i][j] = fmaf(a[i], b[j], acc[i][j]);
        }
        __syncthreads();
    }

#pragma unroll
    for (int i = 0; i < TM; i++) {
        long r = row0 + trow*TM + i;
#pragma unroll
        for (int j = 0; j < TN; j += 4) {
            int c = col0 + tcol*TN + j;
            float4 v;
            v.x = acc[i][j+0]; v.y = acc[i][j+1];
            v.z = acc[i][j+2]; v.w = acc[i][j+3];
            float4 bb = *(const float4*)&bias[c];
            v.x += bb.x; v.y += bb.y; v.z += bb.z; v.w += bb.w;
            *(float4*)&C[r*ldc + c] = v;
        }
    }
}

// ================= QKV f32 -> fp16 =================
__global__ void __launch_bounds__(256)
conv_qkv(const float* __restrict__ QKV, __half* __restrict__ QKVh)
{
    long i = (long)(blockIdx.x * 256 + threadIdx.x) * 4;   // over NTOK*NQKV
    float4 v = *(const float4*)(QKV + i);
    __half2 h0 = __floats2half2_rn(v.x, v.y);
    __half2 h1 = __floats2half2_rn(v.z, v.w);
    uint2 u;
    u.x = *(unsigned*)&h0; u.y = *(unsigned*)&h1;
    *(uint2*)(QKVh + i) = u;
}

// ================= scores via f16 mma: E[h] = exp((Qh@Kh^T)*0.125/temp), fp16 out =================
// CTA: 128x128 tile, K=64 whole. 256 thr = 8 warps in 2(m) x 4(n); warp tile 64x32.
#define SPAD 72
__global__ void __launch_bounds__(256)
scores_mma(const __half* __restrict__ QKVh, __half* __restrict__ E,
           const float* __restrict__ tptr)
{
    __shared__ __half Qs[128 * SPAD];
    __shared__ __half Ks[128 * SPAD];

    const int h    = blockIdx.z;
    const int row0 = blockIdx.y * 128;
    const int col0 = blockIdx.x * 128;
    const int tid  = threadIdx.x;
    const int warp = tid >> 5, lane = tid & 31;
    const int wm = warp & 1, wn = warp >> 1;
    const int lq = lane >> 2;   // 0..7
    const int lr = lane & 3;    // 0..3

    const __half* Qg = QKVh + (long)row0 * NQKV + h * DHEAD;
    const __half* Kg = QKVh + (long)col0 * NQKV + DMODEL + h * DHEAD;

#pragma unroll
    for (int i = tid; i < 128 * 8; i += 256) {   // 8 uint4 (8 halves each) per 64-col row
        int r = i >> 3, c8 = (i & 7) << 3;
        *(uint4*)(Qs + r*SPAD + c8) = *(const uint4*)(Qg + (long)r * NQKV + c8);
        *(uint4*)(Ks + r*SPAD + c8) = *(const uint4*)(Kg + (long)r * NQKV + c8);
    }
    __syncthreads();

    float acc[4][4][4];
#pragma unroll
    for (int a = 0; a < 4; a++)
#pragma unroll
        for (int b = 0; b < 4; b++)
#pragma unroll
            for (int c = 0; c < 4; c++) acc[a][b][c] = 0.f;

#pragma unroll
    for (int kc = 0; kc < 4; kc++) {
        const int ca = kc * 16 + 2*lr;
        unsigned bf[4][2];
#pragma unroll
        for (int nt = 0; nt < 4; nt++) {
            int nb = wn*32 + nt*8 + lq;
            bf[nt][0] = *(const unsigned*)(Ks + nb*SPAD + ca);
            bf[nt][1] = *(const unsigned*)(Ks + nb*SPAD + ca + 8);
        }
#pragma unroll
        for (int mt = 0; mt < 4; mt++) {
            int ra = wm*64 + mt*16 + lq;
            unsigned a0 = *(const unsigned*)(Qs + ra*SPAD + ca);
            unsigned a1 = *(const unsigned*)(Qs + (ra+8)*SPAD + ca);
            unsigned a2 = *(const unsigned*)(Qs + ra*SPAD + ca + 8);
            unsigned a3 = *(const unsigned*)(Qs + (ra+8)*SPAD + ca + 8);
#pragma unroll
            for (int nt = 0; nt < 4; nt++)
                mma_f16(acc[mt][nt], a0, a1, a2, a3, bf[nt][0], bf[nt][1]);
        }
    }

    const float scale = 0.125f / tptr[0];
#pragma unroll
    for (int mt = 0; mt < 4; mt++) {
#pragma unroll
        for (int nt = 0; nt < 4; nt++) {
            int r = row0 + wm*64 + mt*16 + lq;
            int c = col0 + wn*32 + nt*8 + 2*lr;
            __half* b0 = E + ((long)h*NTOK + r)*NTOK + c;
            __half* b1 = E + ((long)h*NTOK + r + 8)*NTOK + c;
            *(__half2*)b0 = __floats2half2_rn(__expf(acc[mt][nt][0]*scale),
                                              __expf(acc[mt][nt][1]*scale));
            *(__half2*)b1 = __floats2half2_rn(__expf(acc[mt][nt][2]*scale),
                                              __expf(acc[mt][nt][3]*scale));
        }
    }
}

// ================= PV via f16 mma: X[h] = P[h] @ V[h], f32 out =================
// CTA: 64 rows x 64 cols, BK=64 chunks. 256 thr = 8 warps in 4(m) x 2(n); warp 16x32.
#define PPAD 72
__global__ void __launch_bounds__(256)
pv_mma(const __half* __restrict__ P, const __half* __restrict__ QKVh,
       float* __restrict__ X)
{
    __shared__ __half Ps[64 * PPAD];
    __shared__ __half Vs[64 * PPAD];

    const int h    = blockIdx.z;
    const int row0 = blockIdx.y * 64;
    const int tid  = threadIdx.x;
    const int warp = tid >> 5, lane = tid & 31;
    const int wm = warp & 3, wn = warp >> 2;
    const int lq = lane >> 2, lr = lane & 3;

    const __half* Pg = P + ((long)h*NTOK + row0) * NTOK;
    const __half* Vg = QKVh + 2*DMODEL + h * DHEAD;   // V block, row stride NQKV

    float acc[4][4];
#pragma unroll
    for (int b = 0; b < 4; b++)
#pragma unroll
        for (int c = 0; c < 4; c++) acc[b][c] = 0.f;

    for (int k0 = 0; k0 < NTOK; k0 += 64) {
        __syncthreads();
        // P tile: 64 rows x 64 halves (8 uint4 per row)
#pragma unroll
        for (int i = tid; i < 512; i += 256) {
            int r = i >> 3, c8 = (i & 7) << 3;
            *(uint4*)(Ps + r*PPAD + c8) = *(const uint4*)(Pg + (long)r * NTOK + k0 + c8);
        }
        // V chunk transposed: Vs[n][k] <- V[k0+k][n]
#pragma unroll
        for (int i = tid; i < 2048; i += 256) {
            int k = i >> 5, np = i & 31;
            unsigned v = *(const unsigned*)(Vg + (long)(k0+k)*NQKV + 2*np);
            __half2 hv = *(__half2*)&v;
            Vs[(2*np)  *PPAD + k] = __low2half(hv);
            Vs[(2*np+1)*PPAD + k] = __high2half(hv);
        }
        __syncthreads();

#pragma unroll
        for (int ks = 0; ks < 4; ks++) {
            const int ca = ks * 16 + 2*lr;
            int ra = wm*16 + lq;
            unsigned a0 = *(const unsigned*)(Ps + ra*PPAD + ca);
            unsigned a1 = *(const unsigned*)(Ps + (ra+8)*PPAD + ca);
            unsigned a2 = *(const unsigned*)(Ps + ra*PPAD + ca + 8);
            unsigned a3 = *(const unsigned*)(Ps + (ra+8)*PPAD + ca + 8);
#pragma unroll
            for (int nt = 0; nt < 4; nt++) {
                int nb = wn*32 + nt*8 + lq;
                unsigned b0 = *(const unsigned*)(Vs + nb*PPAD + ca);
                unsigned b1 = *(const unsigned*)(Vs + nb*PPAD + ca + 8);
                mma_f16(acc[nt], a0, a1, a2, a3, b0, b1);
            }
        }
    }

    int r = row0 + wm*16 + lq;
#pragma unroll
    for (int nt = 0; nt < 4; nt++) {
        int c = h*DHEAD + wn*32 + nt*8 + 2*lr;
        *(float2*)&X[(long)r*DMODEL + c]     = make_float2(acc[nt][0], acc[nt][1]);
        *(float2*)&X[(long)(r+8)*DMODEL + c] = make_float2(acc[nt][2], acc[nt][3]);
    }
}

// ================= mean-shift step (fp16 E) =================
template<bool FINAL>
__global__ void __launch_bounds__(256)
step_kernel(__half* __restrict__ E,
            const float* __restrict__ xyz_in,
            float* __restrict__ xyz_out,
            const float* __restrict__ yhat,
            const int* __restrict__ mask,
            const float* __restrict__ bwptr)
{
    __shared__ float xs[NTOK], ys[NTOK], zs[NTOK], ws[NTOK];
    __shared__ float red[NHEADS][3];

    const int n    = blockIdx.x;
    const int tid  = threadIdx.x;
    const int warp = tid >> 5;
    const int lane = tid & 31;

    const float bw  = bwptr[0];
    const float cbw = 1.0f / (2.0f * bw * bw);
    const float xn = xyz_in[n*3+0];
    const float yn = xyz_in[n*3+1];
    const float zn = xyz_in[n*3+2];
    const float sqn = xn*xn + yn*yn + zn*zn;
    const int* mrow = mask + (long)n * NTOK;

    for (int m = tid; m < NTOK; m += 256) {
        float x = xyz_in[m*3+0];
        float y = xyz_in[m*3+1];
        float z = xyz_in[m*3+2];
        xs[m] = x; ys[m] = y; zs[m] = z;
        float w = __expf(-(sqn + (x*x + y*y + z*z) - 2.f*(xn*x + yn*y + zn*z)) * cbw)
                  * yhat[m] + 1e-9f;
        ws[m] = (mrow[m] > 0) ? w : 0.f;
    }
    __syncthreads();

    __half* Eh = E + ((long)warp * NTOK + n) * NTOK;
    const uint2* Erow = (const uint2*)Eh;

    float Z = 0.f, ax = 0.f, ay = 0.f, az = 0.f;
#pragma unroll 8
    for (int it = 0; it < 16; it++) {
        int i4 = it*32 + lane;
        uint2 ee = Erow[i4];
        float2 e01 = __half22float2(*(__half2*)&ee.x);
        float2 e23 = __half22float2(*(__half2*)&ee.y);
        int j = i4 * 4;
        float4 w  = *(const float4*)&ws[j];
        float4 X  = *(const float4*)&xs[j];
        float4 Y  = *(const float4*)&ys[j];
        float4 Zc = *(const float4*)&zs[j];
        float p0 = e01.x*w.x, p1 = e01.y*w.y, p2 = e23.x*w.z, p3 = e23.y*w.w;
        Z  += (p0 + p1) + (p2 + p3);
        ax = fmaf(p0, X.x, fmaf(p1, X.y, fmaf(p2, X.z, fmaf(p3, X.w, ax))));
        ay = fmaf(p0, Y.x, fmaf(p1, Y.y, fmaf(p2, Y.z, fmaf(p3, Y.w, ay))));
        az = fmaf(p0, Zc.x, fmaf(p1, Zc.y, fmaf(p2, Zc.z, fmaf(p3, Zc.w, az))));
    }

#pragma unroll
    for (int o = 16; o; o >>= 1) {
        Z  += __shfl_xor_sync(0xffffffffu, Z, o);
        ax += __shfl_xor_sync(0xffffffffu, ax, o);
        ay += __shfl_xor_sync(0xffffffffu, ay, o);
        az += __shfl_xor_sync(0xffffffffu, az, o);
    }

    if (FINAL) {
        float invZ = 1.0f / Z;
        uint2* ErowW = (uint2*)Eh;
#pragma unroll 8
        for (int it = 0; it < 16; it++) {
            int i4 = it*32 + lane;
            uint2 ee = Erow[i4];
            float2 e01 = __half22float2(*(__half2*)&ee.x);
            float2 e23 = __half22float2(*(__half2*)&ee.y);
            int j = i4 * 4;
            float4 w = *(const float4*)&ws[j];
            __half2 p01 = __floats2half2_rn(e01.x*w.x*invZ, e01.y*w.y*invZ);
            __half2 p23 = __floats2half2_rn(e23.x*w.z*invZ, e23.y*w.w*invZ);
            uint2 o2;
            o2.x = *(unsigned*)&p01; o2.y = *(unsigned*)&p23;
            ErowW[i4] = o2;
        }
    }

    if (lane == 0) {
        float iZ = 1.0f / Z;
        red[warp][0] = ax * iZ;
        red[warp][1] = ay * iZ;
        red[warp][2] = az * iZ;
    }
    __syncthreads();
    if (tid == 0) {
        float X = 0.f, Y = 0.f, W = 0.f;
#pragma unroll
        for (int hh = 0; hh < NHEADS; hh++) { X += red[hh][0]; Y += red[hh][1]; W += red[hh][2]; }
        xyz_out[n*3+0] = X * 0.125f;
        xyz_out[n*3+1] = Y * 0.125f;
        xyz_out[n*3+2] = W * 0.125f;
    }
}

// ================= host orchestration =================
extern "C" void kernel_launch(void* const* d_in, const int* in_sizes, int n_in,
                              void* d_out, int out_size)
{
    const float* xyz  = (const float*)d_in[0];
    const float* strf = (const float*)d_in[1];
    // d_in[2] esm_feat: dead code in reference
    const float* yhat = (const float*)d_in[3];
    const int*   mask = (const int*)d_in[4];
    const float* t    = (const float*)d_in[5];
    const float* bw   = (const float*)d_in[6];
    // d_in[7] max_iter == 5 (static graph)
    const float* Wq = (const float*)d_in[8];
    const float* bq = (const float*)d_in[9];
    const float* Wk = (const float*)d_in[10];
    const float* bk = (const float*)d_in[11];
    const float* Wv = (const float*)d_in[12];
    const float* bv = (const float*)d_in[13];
    const float* Wo = (const float*)d_in[14];
    const float* bo = (const float*)d_in[15];

    float *QKV, *Wb, *bb, *X, *xyzb;
    __half *QKVh, *E;
    cudaGetSymbolAddress((void**)&QKV,   g_QKV);
    cudaGetSymbolAddress((void**)&QKVh,  g_QKVh);
    cudaGetSymbolAddress((void**)&Wb,    g_W);
    cudaGetSymbolAddress((void**)&bb,    g_b);
    cudaGetSymbolAddress((void**)&E,     g_E);
    cudaGetSymbolAddress((void**)&X,     g_X);
    cudaGetSymbolAddress((void**)&xyzb,  g_xyz);

    float* xyz0 = xyzb;
    float* xyz1 = xyzb + NTOK*3;
    float* outp = (float*)d_out;
    const size_t WSZ = (size_t)DMODEL * DMODEL * sizeof(float);

    cudaMemcpyAsync(Wb + 0*DMODEL*DMODEL, Wq, WSZ, cudaMemcpyDeviceToDevice);
    cudaMemcpyAsync(Wb + 1*DMODEL*DMODEL, Wk, WSZ, cudaMemcpyDeviceToDevice);
    cudaMemcpyAsync(Wb + 2*DMODEL*DMODEL, Wv, WSZ, cudaMemcpyDeviceToDevice);
    cudaMemcpyAsync(bb + 0*DMODEL, bq, DMODEL*sizeof(float), cudaMemcpyDeviceToDevice);
    cudaMemcpyAsync(bb + 1*DMODEL, bk, DMODEL*sizeof(float), cudaMemcpyDeviceToDevice);
    cudaMemcpyAsync(bb + 2*DMODEL, bv, DMODEL*sizeof(float), cudaMemcpyDeviceToDevice);
    cudaMemcpyAsync(xyz0, xyz, NTOK*3*sizeof(float), cudaMemcpyDeviceToDevice);

    dim3 blk(256);

    // fused QKV projection (f32 FFMA)
    gemm_nt<128,128,32,8,8><<<dim3(NQKV/128, NTOK/128, 1), blk>>>(
        DMODEL, strf, DMODEL, Wb, DMODEL, QKV, NQKV, bb);

    // QKV -> fp16
    conv_qkv<<<NTOK*NQKV/4/256, blk>>>(QKV, QKVh);

    // scores (f16 tensor cores) -> E fp16
    scores_mma<<<dim3(NTOK/128, NTOK/128, NHEADS), blk>>>(QKVh, E, t);

    // 5 mean-shift iterations; final writes P (fp16) over E
    step_kernel<false><<<NTOK, blk>>>(E, xyz0, xyz1, yhat, mask, bw);
    step_kernel<false><<<NTOK, blk>>>(E, xyz1, xyz0, yhat, mask, bw);
    step_kernel<false><<<NTOK, blk>>>(E, xyz0, xyz1, yhat, mask, bw);
    step_kernel<false><<<NTOK, blk>>>(E, xyz1, xyz0, yhat, mask, bw);
    step_kernel<true ><<<NTOK, blk>>>(E, xyz0, xyz1, yhat, mask, bw);

    // X[h] = P[h] @ V[h]  (f16 tensor cores)
    pv_mma<<<dim3(1, NTOK/64, NHEADS), blk>>>(E, QKVh, X);

    // out = X @ Wo^T + bo  (f32 FFMA)
    gemm_nt<64,128,32,4,8><<<dim3(DMODEL/128, NTOK/64, 1), blk>>>(
        DMODEL, X, DMODEL, Wo, DMODEL, outp + NTOK*3, DMODEL, bo);

    cudaMemcpyAsync(outp, xyz1, NTOK*3*sizeof(float), cudaMemcpyDeviceToDevice);
}